// round 8
// baseline (speedup 1.0000x reference)
#include <cuda_runtime.h>
#include <cstdint>

// ============================================================================
// SimpleMACELayer — Round 6: mma.sync tf32 pipeline @ 512 threads (16 warps)
// for latency hiding. Warp tile 16e x 32o'. One barrier per q-block.
// ============================================================================

#define EPB 128
#define NTHREADS 512
#define Q_TOTAL 99

__constant__ signed char cQP[Q_TOTAL] = {
    0, 1,1,1, 2,2,2,2,2, 3,3,3,3,3,3,3,
    4,4,4, 5, 6,6,6,6,6, 7,7,7, 8,8,8,8,8,8,8, 9,9,9,9,9,
    10,10,10,10,10, 11,11,11, 12,12,12,12,12,12,12, 13,
    14,14,14,14,14, 15,15,15, 16,16,16,16,16,16,16,
    17,17,17,17,17,17,17, 18,18,18,18,18, 19,19,19,
    20,20,20,20,20,20,20, 21, 22,22,22,22,22};
__constant__ signed char cQKG[Q_TOTAL] = {
    0, 1,2,3, 4,5,6,7,8, 9,10,11,12,13,14,15,
    1,2,3, 0, 4,5,6,7,8, 1,2,3, 9,10,11,12,13,14,15, 4,5,6,7,8,
    4,5,6,7,8, 1,2,3, 9,10,11,12,13,14,15, 0,
    4,5,6,7,8, 1,2,3, 9,10,11,12,13,14,15,
    9,10,11,12,13,14,15, 4,5,6,7,8, 1,2,3,
    9,10,11,12,13,14,15, 0, 4,5,6,7,8};
__constant__ signed char cQJ0[Q_TOTAL] = {
    0, 1,1,1, 4,4,4,4,4, 9,9,9,9,9,9,9,
    0,0,0, 1, 1,1,1,1,1, 4,4,4, 4,4,4,4,4,4,4, 9,9,9,9,9,
    0,0,0,0,0, 1,1,1, 1,1,1,1,1,1,1, 4,
    4,4,4,4,4, 9,9,9, 9,9,9,9,9,9,9,
    0,0,0,0,0,0,0, 1,1,1,1,1, 4,4,4,
    4,4,4,4,4,4,4, 9, 9,9,9,9,9};

__device__ float g_M[Q_TOTAL * 4096];

__device__ __forceinline__ uint32_t tf32r(float x) {
    uint32_t y;
    asm("cvt.rna.tf32.f32 %0, %1;" : "=r"(y) : "f"(x));
    return y;
}
__device__ __forceinline__ void mma8(float* c, const uint32_t* a,
                                     uint32_t b0, uint32_t b1) {
    asm volatile(
        "mma.sync.aligned.m16n8k8.row.col.f32.tf32.tf32.f32 "
        "{%0,%1,%2,%3}, {%4,%5,%6,%7}, {%8,%9}, {%0,%1,%2,%3};"
        : "+f"(c[0]), "+f"(c[1]), "+f"(c[2]), "+f"(c[3])
        : "r"(a[0]), "r"(a[1]), "r"(a[2]), "r"(a[3]), "r"(b0), "r"(b1));
}
__device__ __forceinline__ uint32_t smem_u32(const void* p) {
    uint32_t a;
    asm("{ .reg .u64 t; cvta.to.shared.u64 t, %1; cvt.u32.u64 %0, t; }"
        : "=r"(a) : "l"(p));
    return a;
}
__device__ __forceinline__ void cpasync16(uint32_t dst, const void* src) {
    asm volatile("cp.async.cg.shared.global [%0], [%1], 16;"
                 :: "r"(dst), "l"(src));
}
#define CP_COMMIT() asm volatile("cp.async.commit_group;" ::: "memory")
#define CP_WAIT0()  asm volatile("cp.async.wait_group 0;" ::: "memory")

// ---------------------------------------------------------------------------
__global__ void build_M_kernel(const float* __restrict__ tw,
                               const float* __restrict__ wlin) {
    int q = blockIdx.x, p = cQP[q], kg = cQKG[q];
    __shared__ float twS[4096], wlS[4096];
    for (int i = threadIdx.x; i < 4096; i += blockDim.x) twS[i] = tw[p * 4096 + i];
    for (int i = threadIdx.x; i < 4096; i += blockDim.x) {
        int o = i >> 6, op = i & 63;
        wlS[o * 64 + op] = wlin[op * 1024 + o * 16 + kg];
    }
    __syncthreads();
    for (int r = threadIdx.x; r < 4096; r += blockDim.x) {
        int h = r >> 6, op = r & 63;
        float acc = 0.0f;
#pragma unroll 8
        for (int o = 0; o < 64; ++o) acc += twS[h * 64 + o] * wlS[o * 64 + op];
        g_M[q * 4096 + h * 64 + op] = __uint_as_float(tf32r(acc));
    }
}

__global__ void init_out_kernel(float* __restrict__ out,
                                const float* __restrict__ b, int total) {
    int i = blockIdx.x * blockDim.x + threadIdx.x;
    if (i < total) out[i] = b[i & 63];
}

// ---------------------------------------------------------------------------
// SMEM float offsets (same as R5): total 230400 B
#define SRC_OFF 0
#define U_OFF   14336
#define M_OFF   34816
#define Y_OFF   44032
#define A_OFF   46080
#define CG_OFF  53248
#define IDX_OFF 57344
#define SMEM_TOTAL 230400

#define U_STRIDE 20
#define M_STRIDE 72
#define U_QSZ (128 * U_STRIDE)
#define M_QSZ (16 * M_STRIDE)
#define A_BUFSZ (4 * 7 * 128)

__device__ __forceinline__ void blkMeta(int b, int& g, int& qh, int& qb,
                                        int& nq, int& gath) {
    if (b < 16)      { g = 0; int r = b;      qh = r >> 2; int j = r & 3;
                       qb = 4 * j;        nq = 4;  gath = (j == 0); }
    else if (b < 40) { g = 1; int r = b - 16; qh = r / 6;  int j = r % 6;
                       qb = 16 + 4 * j;   nq = 4;  gath = (j == 0); }
    else if (b < 72) { g = 2; int r = b - 40; qh = r >> 3; int j = r & 7;
                       qb = 40 + 4 * j;   nq = (qb == 68) ? 3 : 4; gath = (j == 0); }
    else             { g = 3; int r = b - 72; qh = r / 7;  int j = r % 7;
                       qb = 71 + 4 * j;   nq = 4;  gath = (j == 0); }
}

__global__ __launch_bounds__(NTHREADS, 1)
void edge_kernel(const float* __restrict__ nf, const float* __restrict__ ev,
                 const int* __restrict__ ei, const float* __restrict__ cg,
                 float* __restrict__ out, int E) {
    extern __shared__ float sm[];
    float* sY = sm + Y_OFF;
    float* sCg = sm + CG_OFF;
    int* sIdx = (int*)(sm + IDX_OFF);
    const int tid = threadIdx.x;
    const int e0 = blockIdx.x * EPB;
    const uint32_t sb = smem_u32(sm);

    for (int i = tid; i < 1024; i += NTHREADS)
        ((float4*)sCg)[i] = ((const float4*)cg)[i];
    if (tid < EPB) {
        int e = e0 + tid;
        if (e < E) {
            float x = ev[e * 3], y = ev[e * 3 + 1], z = ev[e * 3 + 2];
            float x2 = x * x, y2 = y * y, z2 = z * z;
            float Y[16];
            Y[0] = 0.28209479177387814f;
            Y[1] = 0.4886025119029199f * y;
            Y[2] = 0.4886025119029199f * z;
            Y[3] = 0.4886025119029199f * x;
            Y[4] = 1.0925484305920792f * x * y;
            Y[5] = 1.0925484305920792f * y * z;
            Y[6] = 0.31539156525252005f * (3.0f * z2 - 1.0f);
            Y[7] = 1.0925484305920792f * x * z;
            Y[8] = 0.5462742152960396f * (x2 - y2);
            Y[9] = 0.5900435899266435f * y * (3.0f * x2 - y2);
            Y[10] = 2.890611442640554f * x * y * z;
            Y[11] = 0.4570457994644658f * y * (5.0f * z2 - 1.0f);
            Y[12] = 0.3731763325901154f * z * (5.0f * z2 - 3.0f);
            Y[13] = 0.4570457994644658f * x * (5.0f * z2 - 1.0f);
            Y[14] = 1.445305721320277f * z * (x2 - y2);
            Y[15] = 0.5900435899266435f * x * (x2 - 3.0f * y2);
#pragma unroll
            for (int j = 0; j < 16; ++j) sY[j * EPB + tid] = Y[j];
            sIdx[tid] = ei[e];
            sIdx[EPB + tid] = ei[E + e];
        } else {
#pragma unroll
            for (int j = 0; j < 16; ++j) sY[j * EPB + tid] = 0.0f;
            sIdx[tid] = 0;
            sIdx[EPB + tid] = -1;
        }
    }
    __syncthreads();

    auto computeA = [&](int gN, int qbN, int nqN, int dstBuf) {
        const int ncN = 2 * gN + 1, i0N = gN * gN;
        float* dst = sm + A_OFF + dstBuf * A_BUFSZ;
        for (int idx = tid; idx < nqN * ncN * 128; idx += NTHREADS) {
            int e = idx & 127, r = idx >> 7;
            int ic = r % ncN, qq = r / ncN, q = qbN + qq;
            int j0 = cQJ0[q], kg = cQKG[q];
            int nj = (j0 == 0) ? 1 : (j0 == 1) ? 3 : (j0 == 4) ? 5 : 7;
            const float* cgp = sCg + (i0N + ic) * 256 + j0 * 16 + kg;
            float a = 0.0f;
#pragma unroll
            for (int jc = 0; jc < 7; ++jc)
                if (jc < nj) a += sY[(j0 + jc) * EPB + e] * cgp[jc * 16];
            dst[(qq * 7 + ic) * 128 + e] = a;
        }
    };

    {
        int g, qh, qb, nq, ga;
        blkMeta(0, g, qh, qb, nq, ga);
        computeA(g, qb, nq, 0);
    }

    // 16 warps: wy = e-tile (8, 16 rows each), wx = o'-half (2)
    const int lane = tid & 31, gid = lane >> 2, tig = lane & 3;
    const int wid = tid >> 5, wy = wid & 7, wx = wid >> 3;
    float acc[4][4];
#pragma unroll
    for (int nt = 0; nt < 4; ++nt)
#pragma unroll
        for (int r = 0; r < 4; ++r) acc[nt][r] = 0.0f;

    int prevBuf = -1, prevNq = 0, buf = 0;

    for (int b = 0; b < 100; ++b) {
        int g, qh, qb, nq, doGather;
        blkMeta(b, g, qh, qb, nq, doGather);
        const int nc = 2 * g + 1;

        __syncthreads();

        // ---- mma(prev): warp tile 16e x 32o' ----
        if (prevBuf >= 0) {
            for (int qq = 0; qq < prevNq; ++qq) {
                const float* Ub = sm + U_OFF + (prevBuf * 4 + qq) * U_QSZ;
                const float* Mb = sm + M_OFF + (prevBuf * 4 + qq) * M_QSZ;
#pragma unroll
                for (int ks = 0; ks < 2; ++ks) {
                    const int k0 = ks * 8;
                    uint32_t a[4];
                    {
                        const float* up =
                            Ub + (wy * 16 + gid) * U_STRIDE + k0 + tig;
                        a[0] = __float_as_uint(up[0]);
                        a[1] = __float_as_uint(up[8 * U_STRIDE]);
                        a[2] = __float_as_uint(up[4]);
                        a[3] = __float_as_uint(up[8 * U_STRIDE + 4]);
                    }
#pragma unroll
                    for (int nt = 0; nt < 4; ++nt) {
                        const float* mp =
                            Mb + (k0 + tig) * M_STRIDE + wx * 32 + nt * 8 + gid;
                        uint32_t b0 = __float_as_uint(mp[0]);
                        uint32_t b1 = __float_as_uint(mp[4 * M_STRIDE]);
                        mma8(acc[nt], a, b0, b1);
                    }
                }
            }
        }

        // ---- gather sSrc[ic][e][hh16] ----
        if (doGather) {
            float* sSrc = sm + SRC_OFF;
            for (int idx = tid; idx < 2048; idx += NTHREADS) {
                int e = idx >> 4, hh = idx & 15;
                const float* base =
                    nf + (size_t)sIdx[e] * 1024 + (qh * 16 + hh) * 16;
                float* d = sSrc + e * 16 + hh;
                if (g == 0) {
                    d[0] = __ldg(base);
                } else if (g == 1) {
                    float4 v = __ldg((const float4*)base);
                    d[0] = v.y; d[2048] = v.z; d[4096] = v.w;
                } else if (g == 2) {
                    float4 v = __ldg((const float4*)(base + 4));
                    float s = __ldg(base + 8);
                    d[0] = v.x; d[2048] = v.y; d[4096] = v.z;
                    d[6144] = v.w; d[8192] = s;
                } else {
                    float4 va = __ldg((const float4*)(base + 8));
                    float4 vb = __ldg((const float4*)(base + 12));
                    d[0] = va.y; d[2048] = va.z; d[4096] = va.w;
                    d[6144] = vb.x; d[8192] = vb.y; d[10240] = vb.z;
                    d[12288] = vb.w;
                }
            }
            __syncthreads();
        }

        // ---- fill(cur) ----
        {
            const int nW = nq * 256;
            for (int idx = tid; idx < nW; idx += NTHREADS) {
                int qq = idx >> 8, w = idx & 255;
                int h = w >> 4, o4 = w & 15;
                const float* src =
                    g_M + (qb + qq) * 4096 + (qh * 16 + h) * 64 + o4 * 4;
                uint32_t dst = sb + 4 * (M_OFF + (buf * 4 + qq) * M_QSZ +
                                         h * M_STRIDE + o4 * 4);
                cpasync16(dst, src);
            }
            CP_COMMIT();
        }
        if (b + 1 < 100) {
            int gN, qhN, qbN, nqN, gaN;
            blkMeta(b + 1, gN, qhN, qbN, nqN, gaN);
            computeA(gN, qbN, nqN, buf ^ 1);
        }
        {
            const float4* s4 = (const float4*)(sm + SRC_OFF);
            const float* aB = sm + A_OFF + buf * A_BUFSZ;
            int e = tid >> 2, hv = tid & 3;   // 512 threads: exactly one item
            float4 s[7];
#pragma unroll
            for (int ic = 0; ic < 7; ++ic)
                if (ic < nc) s[ic] = s4[(ic * 128 + e) * 4 + hv];
            for (int qq = 0; qq < nq; ++qq) {
                float4 u = {0.f, 0.f, 0.f, 0.f};
#pragma unroll
                for (int ic = 0; ic < 7; ++ic)
                    if (ic < nc) {
                        float a = aB[(qq * 7 + ic) * 128 + e];
                        u.x += a * s[ic].x; u.y += a * s[ic].y;
                        u.z += a * s[ic].z; u.w += a * s[ic].w;
                    }
                uint4 t = {tf32r(u.x), tf32r(u.y), tf32r(u.z), tf32r(u.w)};
                *(uint4*)(sm + U_OFF + (buf * 4 + qq) * U_QSZ +
                          e * U_STRIDE + hv * 4) = t;
            }
        }
        CP_WAIT0();
        prevBuf = buf; prevNq = nq; buf ^= 1;
    }

    // ---- final mma ----
    __syncthreads();
    for (int qq = 0; qq < prevNq; ++qq) {
        const float* Ub = sm + U_OFF + (prevBuf * 4 + qq) * U_QSZ;
        const float* Mb = sm + M_OFF + (prevBuf * 4 + qq) * M_QSZ;
#pragma unroll
        for (int ks = 0; ks < 2; ++ks) {
            const int k0 = ks * 8;
            uint32_t a[4];
            {
                const float* up = Ub + (wy * 16 + gid) * U_STRIDE + k0 + tig;
                a[0] = __float_as_uint(up[0]);
                a[1] = __float_as_uint(up[8 * U_STRIDE]);
                a[2] = __float_as_uint(up[4]);
                a[3] = __float_as_uint(up[8 * U_STRIDE + 4]);
            }
#pragma unroll
            for (int nt = 0; nt < 4; ++nt) {
                const float* mp =
                    Mb + (k0 + tig) * M_STRIDE + wx * 32 + nt * 8 + gid;
                uint32_t b0 = __float_as_uint(mp[0]);
                uint32_t b1 = __float_as_uint(mp[4 * M_STRIDE]);
                mma8(acc[nt], a, b0, b1);
            }
        }
    }

    // ---- epilogue ----
#pragma unroll
    for (int r = 0; r < 2; ++r) {
        int e = wy * 16 + gid + r * 8;
        int dst = sIdx[EPB + e];
        if (dst >= 0) {
            float* op = out + (size_t)dst * 64 + wx * 32 + 2 * tig;
#pragma unroll
            for (int nt = 0; nt < 4; ++nt) {
                float2 v = make_float2(acc[nt][r * 2], acc[nt][r * 2 + 1]);
                atomicAdd((float2*)(op + nt * 8), v);
            }
        }
    }
}

// ---------------------------------------------------------------------------
extern "C" void kernel_launch(void* const* d_in, const int* in_sizes, int n_in,
                              void* d_out, int out_size) {
    const float* nf = (const float*)d_in[0];
    const float* ev = (const float*)d_in[1];
    const int* ei = (const int*)d_in[2];
    const float* cg = (const float*)d_in[3];
    const float* tw = (const float*)d_in[4];
    const float* wlin = (const float*)d_in[5];
    const float* bl = (const float*)d_in[6];
    float* out = (float*)d_out;
    const int E = in_sizes[1] / 3;
    const int N = in_sizes[0] / 1024;

    cudaFuncSetAttribute(edge_kernel,
                         cudaFuncAttributeMaxDynamicSharedMemorySize, SMEM_TOTAL);
    build_M_kernel<<<Q_TOTAL, 256>>>(tw, wlin);
    init_out_kernel<<<(N * 64 + 255) / 256, 256>>>(out, bl, N * 64);
    edge_kernel<<<(E + EPB - 1) / EPB, NTHREADS, SMEM_TOTAL>>>(nf, ev, ei, cg, out, E);
}

// round 9
// speedup vs baseline: 2.6873x; 2.6873x over previous
#include <cuda_runtime.h>
#include <cuda_fp16.h>
#include <cstdint>

// ============================================================================
// SimpleMACELayer — Round 8: fp16 mma.sync (m16n8k16), 2 CTAs/SM.
// R4 skeleton (3 barriers/chunk), fp16 U/M/src storage, fp32 accumulators.
// ============================================================================

#define EPB 128
#define NTHREADS 256
#define Q_TOTAL 99

__constant__ signed char cQP[Q_TOTAL] = {
    0, 1,1,1, 2,2,2,2,2, 3,3,3,3,3,3,3,
    4,4,4, 5, 6,6,6,6,6, 7,7,7, 8,8,8,8,8,8,8, 9,9,9,9,9,
    10,10,10,10,10, 11,11,11, 12,12,12,12,12,12,12, 13,
    14,14,14,14,14, 15,15,15, 16,16,16,16,16,16,16,
    17,17,17,17,17,17,17, 18,18,18,18,18, 19,19,19,
    20,20,20,20,20,20,20, 21, 22,22,22,22,22};
__constant__ signed char cQKG[Q_TOTAL] = {
    0, 1,2,3, 4,5,6,7,8, 9,10,11,12,13,14,15,
    1,2,3, 0, 4,5,6,7,8, 1,2,3, 9,10,11,12,13,14,15, 4,5,6,7,8,
    4,5,6,7,8, 1,2,3, 9,10,11,12,13,14,15, 0,
    4,5,6,7,8, 1,2,3, 9,10,11,12,13,14,15,
    9,10,11,12,13,14,15, 4,5,6,7,8, 1,2,3,
    9,10,11,12,13,14,15, 0, 4,5,6,7,8};
__constant__ signed char cQJ0[Q_TOTAL] = {
    0, 1,1,1, 4,4,4,4,4, 9,9,9,9,9,9,9,
    0,0,0, 1, 1,1,1,1,1, 4,4,4, 4,4,4,4,4,4,4, 9,9,9,9,9,
    0,0,0,0,0, 1,1,1, 1,1,1,1,1,1,1, 4,
    4,4,4,4,4, 9,9,9, 9,9,9,9,9,9,9,
    0,0,0,0,0,0,0, 1,1,1,1,1, 4,4,4,
    4,4,4,4,4,4,4, 9, 9,9,9,9,9};
__constant__ int cPSTART[5] = {0, 16, 40, 71, 99};

// Fused weights, fp16, o'-major: g_Mh[q][o'][h]  (99*64*64 halves = 811KB)
__device__ __half g_Mh[Q_TOTAL * 4096];

__device__ __forceinline__ void mma16(float* c, const uint32_t* a,
                                      uint32_t b0, uint32_t b1) {
    asm volatile(
        "mma.sync.aligned.m16n8k16.row.col.f32.f16.f16.f32 "
        "{%0,%1,%2,%3}, {%4,%5,%6,%7}, {%8,%9}, {%0,%1,%2,%3};"
        : "+f"(c[0]), "+f"(c[1]), "+f"(c[2]), "+f"(c[3])
        : "r"(a[0]), "r"(a[1]), "r"(a[2]), "r"(a[3]), "r"(b0), "r"(b1));
}

// ---------------------------------------------------------------------------
__global__ void build_M_kernel(const float* __restrict__ tw,
                               const float* __restrict__ wlin) {
    int q = blockIdx.x, p = cQP[q], kg = cQKG[q];
    __shared__ float twS[4096], wlS[4096];
    for (int i = threadIdx.x; i < 4096; i += blockDim.x) twS[i] = tw[p * 4096 + i];
    for (int i = threadIdx.x; i < 4096; i += blockDim.x) {
        int o = i >> 6, op = i & 63;
        wlS[o * 64 + op] = wlin[op * 1024 + o * 16 + kg];
    }
    __syncthreads();
    for (int r = threadIdx.x; r < 4096; r += blockDim.x) {
        int h = r >> 6, op = r & 63;
        float acc = 0.0f;
#pragma unroll 8
        for (int o = 0; o < 64; ++o) acc += twS[h * 64 + o] * wlS[o * 64 + op];
        g_Mh[q * 4096 + op * 64 + h] = __float2half_rn(acc);   // [q][o'][h]
    }
}

__global__ void init_out_kernel(float* __restrict__ out,
                                const float* __restrict__ b, int total) {
    int i = blockIdx.x * blockDim.x + threadIdx.x;
    if (i < total) out[i] = b[i & 63];
}

// ---------------------------------------------------------------------------
// SMEM layout (bytes):
//   sSrc half [ic7][e128][hh32]            0     57344
//   sU   half [q2][e128][40]           57344     20480   (row 80B, 16B-align)
//   sM   half [q2][o64][40]            77824     10240
//   sY   f32  [j16][e128]              88064      8192
//   sA   f32  [q2*7][e128]             96256      7168
//   sIdx i32  [2][128]                103424      1024
// total 104448 B  -> 2 CTAs/SM
#define U_OFF   57344
#define M_OFF   77824
#define Y_OFF   88064
#define A_OFF   96256
#define IDX_OFF 103424
#define SMEM_TOTAL 104448

#define U_STRIDE 40   // halves
#define M_STRIDE 40   // halves
#define U_QSZ (128 * U_STRIDE)
#define M_QSZ (64 * M_STRIDE)

__global__ __launch_bounds__(NTHREADS, 2)
void edge_kernel(const float* __restrict__ nf, const float* __restrict__ ev,
                 const int* __restrict__ ei, const float* __restrict__ cg,
                 float* __restrict__ out, int E) {
    extern __shared__ char smx[];
    __half* sSrc = (__half*)smx;
    __half* sU = (__half*)(smx + U_OFF);
    __half* sM = (__half*)(smx + M_OFF);
    float* sY = (float*)(smx + Y_OFF);
    float* sA = (float*)(smx + A_OFF);
    int* sIdx = (int*)(smx + IDX_OFF);
    const int tid = threadIdx.x;
    const int e0 = blockIdx.x * EPB;

    // ---- Y + indices ----
    if (tid < EPB) {
        int e = e0 + tid;
        if (e < E) {
            float x = ev[e * 3], y = ev[e * 3 + 1], z = ev[e * 3 + 2];
            float x2 = x * x, y2 = y * y, z2 = z * z;
            float Y[16];
            Y[0] = 0.28209479177387814f;
            Y[1] = 0.4886025119029199f * y;
            Y[2] = 0.4886025119029199f * z;
            Y[3] = 0.4886025119029199f * x;
            Y[4] = 1.0925484305920792f * x * y;
            Y[5] = 1.0925484305920792f * y * z;
            Y[6] = 0.31539156525252005f * (3.0f * z2 - 1.0f);
            Y[7] = 1.0925484305920792f * x * z;
            Y[8] = 0.5462742152960396f * (x2 - y2);
            Y[9] = 0.5900435899266435f * y * (3.0f * x2 - y2);
            Y[10] = 2.890611442640554f * x * y * z;
            Y[11] = 0.4570457994644658f * y * (5.0f * z2 - 1.0f);
            Y[12] = 0.3731763325901154f * z * (5.0f * z2 - 3.0f);
            Y[13] = 0.4570457994644658f * x * (5.0f * z2 - 1.0f);
            Y[14] = 1.445305721320277f * z * (x2 - y2);
            Y[15] = 0.5900435899266435f * x * (x2 - 3.0f * y2);
#pragma unroll
            for (int j = 0; j < 16; ++j) sY[j * EPB + tid] = Y[j];
            sIdx[tid] = ei[e];
            sIdx[EPB + tid] = ei[E + e];
        } else {
#pragma unroll
            for (int j = 0; j < 16; ++j) sY[j * EPB + tid] = 0.0f;
            sIdx[tid] = 0;
            sIdx[EPB + tid] = -1;
        }
    }

    const int lane = tid & 31, gid = lane >> 2, tig = lane & 3;
    const int wy = (tid >> 5) & 3;   // e-tile (4 x 32 rows)
    const int wx = tid >> 7;         // o'-half (2 x 32 cols)
    float acc[2][4][4];
#pragma unroll
    for (int mt = 0; mt < 2; ++mt)
#pragma unroll
        for (int nt = 0; nt < 4; ++nt)
#pragma unroll
            for (int r = 0; r < 4; ++r) acc[mt][nt][r] = 0.0f;
    __syncthreads();

    for (int g = 0; g < 4; ++g) {
        const int nc = 2 * g + 1, i0 = g * g;
        for (int half = 0; half < 2; ++half) {
            // ---- gather sSrc[ic][e][hh] (vectorized over irreps, fp16 store)
            for (int idx = tid; idx < EPB * 32; idx += NTHREADS) {
                int e = idx >> 5, hh = idx & 31;
                const float* base =
                    nf + (size_t)sIdx[e] * 1024 + (half * 32 + hh) * 16;
                __half* d = sSrc + e * 32 + hh;  // + ic*4096
                if (g == 0) {
                    d[0] = __float2half_rn(__ldg(base));
                } else if (g == 1) {
                    float4 v = __ldg((const float4*)base);
                    d[0] = __float2half_rn(v.y);
                    d[4096] = __float2half_rn(v.z);
                    d[8192] = __float2half_rn(v.w);
                } else if (g == 2) {
                    float4 v = __ldg((const float4*)(base + 4));
                    float s = __ldg(base + 8);
                    d[0] = __float2half_rn(v.x);
                    d[4096] = __float2half_rn(v.y);
                    d[8192] = __float2half_rn(v.z);
                    d[12288] = __float2half_rn(v.w);
                    d[16384] = __float2half_rn(s);
                } else {
                    float4 va = __ldg((const float4*)(base + 8));
                    float4 vb = __ldg((const float4*)(base + 12));
                    d[0] = __float2half_rn(va.y);
                    d[4096] = __float2half_rn(va.z);
                    d[8192] = __float2half_rn(va.w);
                    d[12288] = __float2half_rn(vb.x);
                    d[16384] = __float2half_rn(vb.y);
                    d[20480] = __float2half_rn(vb.z);
                    d[24576] = __float2half_rn(vb.w);
                }
            }
            __syncthreads();

            const int qend = cPSTART[g + 1];
            for (int qb = cPSTART[g]; qb < qend; qb += 2) {
                const int nqc = (qend - qb >= 2) ? 2 : 1;

                // ---- phase A: A-coeffs (fp32) + M tile copy (fp16) ----
                for (int idx = tid; idx < nqc * nc * EPB; idx += NTHREADS) {
                    int e = idx & 127, r = idx >> 7;
                    int ic = r % nc, qq = r / nc, q = qb + qq;
                    int j0 = cQJ0[q], kg = cQKG[q];
                    int nj = (j0 == 0) ? 1 : (j0 == 1) ? 3 : (j0 == 4) ? 5 : 7;
                    const float* cgp = cg + (i0 + ic) * 256 + j0 * 16 + kg;
                    float a = 0.0f;
#pragma unroll
                    for (int jc = 0; jc < 7; ++jc)
                        if (jc < nj) a += sY[(j0 + jc) * EPB + e] * __ldg(cgp + jc * 16);
                    sA[(qq * 7 + ic) * EPB + e] = a;
                }
                for (int idx = tid; idx < nqc * 256; idx += NTHREADS) {
                    int qq = idx >> 8, w = idx & 255;
                    int o = w >> 2, seg = w & 3;   // 4 x 8 halves per o-row
                    uint4 v = *(const uint4*)(g_Mh + (qb + qq) * 4096 + o * 64 +
                                              half * 32 + seg * 8);
                    *(uint4*)(sM + qq * M_QSZ + o * M_STRIDE + seg * 8) = v;
                }
                __syncthreads();

                // ---- phase B: U tiles (fp32 math, fp16 store) ----
                for (int idx = tid; idx < EPB * 8; idx += NTHREADS) {
                    int e = idx >> 3, hv = idx & 7;   // 4 h's per item
                    float u[2][4];
#pragma unroll
                    for (int qq = 0; qq < 2; ++qq)
#pragma unroll
                        for (int r = 0; r < 4; ++r) u[qq][r] = 0.0f;
#pragma unroll
                    for (int ic = 0; ic < 7; ++ic)
                        if (ic < nc) {
                            uint2 sw = *(const uint2*)(sSrc + ic * 4096 +
                                                       e * 32 + hv * 4);
                            float2 f0 = __half22float2(*(__half2*)&sw.x);
                            float2 f1 = __half22float2(*(__half2*)&sw.y);
                            float a0 = sA[ic * EPB + e];
                            u[0][0] += a0 * f0.x; u[0][1] += a0 * f0.y;
                            u[0][2] += a0 * f1.x; u[0][3] += a0 * f1.y;
                            if (nqc == 2) {
                                float a1 = sA[(7 + ic) * EPB + e];
                                u[1][0] += a1 * f0.x; u[1][1] += a1 * f0.y;
                                u[1][2] += a1 * f1.x; u[1][3] += a1 * f1.y;
                            }
                        }
                    {
                        __half2 p0 = __floats2half2_rn(u[0][0], u[0][1]);
                        __half2 p1 = __floats2half2_rn(u[0][2], u[0][3]);
                        uint2 st = {*(uint32_t*)&p0, *(uint32_t*)&p1};
                        *(uint2*)(sU + e * U_STRIDE + hv * 4) = st;
                    }
                    if (nqc == 2) {
                        __half2 p0 = __floats2half2_rn(u[1][0], u[1][1]);
                        __half2 p1 = __floats2half2_rn(u[1][2], u[1][3]);
                        uint2 st = {*(uint32_t*)&p0, *(uint32_t*)&p1};
                        *(uint2*)(sU + U_QSZ + e * U_STRIDE + hv * 4) = st;
                    }
                }
                __syncthreads();

                // ---- mma phase: warp tile 32e x 32o', K = 32 per q ----
                for (int qq = 0; qq < nqc; ++qq) {
                    const __half* Ub = sU + qq * U_QSZ;
                    const __half* Mb = sM + qq * M_QSZ;
#pragma unroll
                    for (int ks = 0; ks < 2; ++ks) {
                        const int k0 = ks * 16 + 2 * tig;
                        uint32_t a[2][4];
#pragma unroll
                        for (int mt = 0; mt < 2; ++mt) {
                            const __half* up =
                                Ub + (wy * 32 + mt * 16 + gid) * U_STRIDE + k0;
                            a[mt][0] = *(const uint32_t*)(up);
                            a[mt][1] = *(const uint32_t*)(up + 8 * U_STRIDE);
                            a[mt][2] = *(const uint32_t*)(up + 8);
                            a[mt][3] = *(const uint32_t*)(up + 8 * U_STRIDE + 8);
                        }
#pragma unroll
                        for (int nt = 0; nt < 4; ++nt) {
                            const __half* mp =
                                Mb + (wx * 32 + nt * 8 + gid) * M_STRIDE + k0;
                            uint32_t b0 = *(const uint32_t*)(mp);
                            uint32_t b1 = *(const uint32_t*)(mp + 8);
                            mma16(acc[0][nt], a[0], b0, b1);
                            mma16(acc[1][nt], a[1], b0, b1);
                        }
                    }
                }
                __syncthreads();
            }
        }
    }

    // ---- epilogue: float2 atomics into out[dst] ----
#pragma unroll
    for (int mt = 0; mt < 2; ++mt)
#pragma unroll
        for (int r = 0; r < 2; ++r) {
            int e = wy * 32 + mt * 16 + gid + r * 8;
            int dst = sIdx[EPB + e];
            if (dst >= 0) {
                float* op = out + (size_t)dst * 64 + wx * 32 + 2 * tig;
#pragma unroll
                for (int nt = 0; nt < 4; ++nt) {
                    float2 v = make_float2(acc[mt][nt][r * 2],
                                           acc[mt][nt][r * 2 + 1]);
                    atomicAdd((float2*)(op + nt * 8), v);
                }
            }
        }
}

// ---------------------------------------------------------------------------
extern "C" void kernel_launch(void* const* d_in, const int* in_sizes, int n_in,
                              void* d_out, int out_size) {
    const float* nf = (const float*)d_in[0];
    const float* ev = (const float*)d_in[1];
    const int* ei = (const int*)d_in[2];
    const float* cg = (const float*)d_in[3];
    const float* tw = (const float*)d_in[4];
    const float* wlin = (const float*)d_in[5];
    const float* bl = (const float*)d_in[6];
    float* out = (float*)d_out;
    const int E = in_sizes[1] / 3;
    const int N = in_sizes[0] / 1024;

    cudaFuncSetAttribute(edge_kernel,
                         cudaFuncAttributeMaxDynamicSharedMemorySize, SMEM_TOTAL);
    build_M_kernel<<<Q_TOTAL, 256>>>(tw, wlin);
    init_out_kernel<<<(N * 64 + 255) / 256, 256>>>(out, bl, N * 64);
    edge_kernel<<<(E + EPB - 1) / EPB, NTHREADS, SMEM_TOTAL>>>(nf, ev, ei, cg, out, E);
}